// round 3
// baseline (speedup 1.0000x reference)
#include <cuda_runtime.h>

#define S 32
#define CCH 3
#define NSTEPS 4
#define DT_C 0.15f
#define EPS_C 1e-6f

// Precomputed Thomas factors: p = 1/denom, q = a/denom (== cstar since a==c).
// Layout: [step][channel][line][i] as float2, contiguous in (line,i) per step.
__device__ float2 g_pqx[NSTEPS * CCH * S * S];
__device__ float2 g_pqy[NSTEPS * CCH * S * S];

__global__ void precompute_kernel(const float* __restrict__ alpha_base,
                                  const float* __restrict__ beta_base,
                                  const float* __restrict__ alpha_tc,
                                  const float* __restrict__ beta_tc) {
    int idx = blockIdx.x * blockDim.x + threadIdx.x;
    const int NLINES = NSTEPS * CCH * S;      // 384 per direction
    if (idx >= 2 * NLINES) return;
    int dir  = idx / NLINES;                  // 0 = x (solve along W), 1 = y (along H)
    int r    = idx % NLINES;
    int t    = r / (CCH * S);
    int c    = (r / S) % CCH;
    int line = r % S;                          // h for x-dir, w for y-dir

    float tv = (float)t * DT_C;
    const float* base = dir ? beta_base : alpha_base;
    const float* tc   = dir ? beta_tc   : alpha_tc;

    float raw[S];
    #pragma unroll
    for (int i = 0; i < S; i++) {
        int h = dir ? i : line;
        int w = dir ? line : i;
        int off = (c * S + h) * S + w;
        raw[i] = fmaxf(base[off] + tc[off] * tv, EPS_C);
    }
    // 3-tap replicate-padded smoothing along the solve dimension, times dt/DX^2
    float dt = dir ? DT_C : (DT_C * 0.5f);
    float cf[S];
    #pragma unroll
    for (int i = 0; i < S; i++) {
        float lm = raw[i == 0 ? 0 : i - 1];
        float rm = raw[i == S - 1 ? S - 1 : i + 1];
        cf[i] = (lm + raw[i] + rm) * (1.0f / 3.0f) * dt;
    }
    float2* out = dir ? g_pqy : g_pqx;
    long ob = ((long)(t * CCH + c) * S + line) * S;
    float cp = 0.0f;
    #pragma unroll
    for (int i = 0; i < S; i++) {
        float b = 1.0f + 2.0f * cf[i];
        if (i == 0 || i == S - 1) b = 1.0f + cf[i];
        float a = -cf[i];
        float denom = b - a * cp + EPS_C;     // matches reference (+EPS every step)
        float p = 1.0f / denom;
        float q = a * p;                      // also equals cstar_i (a == c)
        cp = q;
        out[ob + i] = make_float2(p, q);
    }
}

// One tridiagonal sweep of 32 independent systems (lane = batch) for one line.
// Coefficients come from a per-line smem table via LDS.128 *broadcast* (all
// lanes read the same address -> 1 wavefront each), replacing 95 SHFLs/solve
// with 32 broadcast loads. cf[j] = {p_{2j}, q_{2j}, p_{2j+1}, q_{2j+1}}.
template<bool COL, bool IN_SMEM, bool OUT_SMEM>
__device__ __forceinline__ void solve32(float* __restrict__ tile, float (&r)[S],
                                        const float4* __restrict__ cf,
                                        int line, int lane, float scale) {
    float prev = 0.0f;
    #pragma unroll
    for (int j = 0; j < S / 2; j++) {
        float4 v = cf[j];
        int i0 = 2 * j;
        float d0;
        if (IN_SMEM) {
            int e = COL ? (i0 * S + line) : (line * S + i0);
            d0 = tile[e * 33 + lane];
        } else d0 = r[i0];
        prev = fmaf(-v.y, prev, d0 * v.x);    // (d - a*prev)/denom
        r[i0] = prev;
        float d1;
        if (IN_SMEM) {
            int e = COL ? ((i0 + 1) * S + line) : (line * S + i0 + 1);
            d1 = tile[e * 33 + lane];
        } else d1 = r[i0 + 1];
        prev = fmaf(-v.w, prev, d1 * v.z);
        r[i0 + 1] = prev;
    }
    float x = r[S - 1];                        // cstar[N-1] irrelevant
    r[S - 1] = x * scale;
    if (OUT_SMEM) {
        int e = COL ? ((S - 1) * S + line) : (line * S + (S - 1));
        tile[e * 33 + lane] = x * scale;
    }
    #pragma unroll
    for (int j = S / 2 - 1; j >= 0; j--) {
        float4 v = cf[j];
        if (j < S / 2 - 1) {
            int i = 2 * j + 1;
            x = fmaf(-v.w, x, r[i]);           // cstar_i == q_i
            r[i] = x * scale;
            if (OUT_SMEM) {
                int e = COL ? (i * S + line) : (line * S + i);
                tile[e * 33 + lane] = x * scale;
            }
        }
        int i = 2 * j;
        x = fmaf(-v.y, x, r[i]);
        r[i] = x * scale;
        if (OUT_SMEM) {
            int e = COL ? (i * S + line) : (line * S + i);
            tile[e * 33 + lane] = x * scale;
        }
    }
}

// Dynamic smem: [ scx4: 2048 float4 | scy4: 2048 float4 | tile: 33792 floats ]
#define COEF_F4_PER_DIR (NSTEPS * S * (S / 2))   // 2048 float4 = 32KB per dir
#define SMEM_BYTES (2 * COEF_F4_PER_DIR * 16 + S * S * 33 * 4)  // 200704 B

__global__ void __launch_bounds__(1024, 1)
adi_kernel(const float* __restrict__ U, const float* __restrict__ coupling,
           float* __restrict__ Out) {
    extern __shared__ float smem[];
    float4* scx4 = (float4*)smem;
    float4* scy4 = scx4 + COEF_F4_PER_DIR;
    float*  tile = (float*)(scy4 + COEF_F4_PER_DIR);

    int c    = blockIdx.x % CCH;
    int g    = blockIdx.x / CCH;
    int warp = threadIdx.x >> 5;
    int lane = threadIdx.x & 31;
    int tid  = threadIdx.x;

    // Stage this channel's (p,q) tables into smem (4 steps x 32 lines x 16 f4).
    const float4* gx4 = (const float4*)g_pqx;
    const float4* gy4 = (const float4*)g_pqy;
    #pragma unroll
    for (int k = tid; k < NSTEPS * 512; k += 1024) {
        int t = k >> 9;                        // 512 float4 per step per dir
        int j = k & 511;
        scx4[t * 512 + j] = gx4[(t * CCH + c) * 512 + j];
        scy4[t * 512 + j] = gy4[(t * CCH + c) * 512 + j];
    }

    size_t base = ((size_t)g * S) * (CCH * S * S) + (size_t)c * (S * S);
    const float* ub = U + base + (size_t)warp * (CCH * S * S);  // batch = g*32+warp

    // Coalesced load (128B/line) -> conflict-free STS thanks to the 33-pad.
    #pragma unroll
    for (int k = 0; k < S; k++)
        tile[(k * S + lane) * 33 + warp] = __ldg(ub + k * S + lane);

    float scal = coupling[c * CCH + c];       // einsum 'cc,bchw->bchw' = diag scale
    __syncthreads();

    float r[S];
    #pragma unroll 1
    for (int t = 0; t < NSTEPS; t++) {
        const float4* cfx = scx4 + (t * S + warp) * (S / 2);
        const float4* cfy = scy4 + (t * S + warp) * (S / 2);

        // x half-step #1: rows. Input comes from registers for t>0 (fused with
        // previous step's x2 output, same warp/lane/addresses -> no barrier).
        if (t == 0) solve32<false, true,  true>(tile, r, cfx, warp, lane, 1.0f);
        else        solve32<false, false, true>(tile, r, cfx, warp, lane, 1.0f);
        __syncthreads();

        // y full step: columns (r reused as scratch; rows already flushed).
        solve32<true, true, true>(tile, r, cfy, warp, lane, 1.0f);
        __syncthreads();

        // x half-step #2: rows, with channel coupling folded into the output.
        // For t<3 keep the result in registers only (next x1 consumes it).
        if (t == NSTEPS - 1) solve32<false, true, true >(tile, r, cfx, warp, lane, scal);
        else                 solve32<false, true, false>(tile, r, cfx, warp, lane, scal);
        if (t == NSTEPS - 1) __syncthreads();
    }

    float* ob = Out + base + (size_t)warp * (CCH * S * S);
    #pragma unroll
    for (int k = 0; k < S; k++)
        ob[k * S + lane] = tile[(k * S + lane) * 33 + warp];
}

extern "C" void kernel_launch(void* const* d_in, const int* in_sizes, int n_in,
                              void* d_out, int out_size) {
    (void)n_in; (void)out_size;
    const float* u   = (const float*)d_in[0];
    const float* ab  = (const float*)d_in[1];
    const float* bb  = (const float*)d_in[2];
    const float* atc = (const float*)d_in[3];
    const float* btc = (const float*)d_in[4];
    const float* cc  = (const float*)d_in[5];
    int B = in_sizes[0] / (CCH * S * S);      // 16384

    cudaFuncSetAttribute(adi_kernel, cudaFuncAttributeMaxDynamicSharedMemorySize,
                         SMEM_BYTES);

    precompute_kernel<<<3, 256>>>(ab, bb, atc, btc);   // 768 lines, trivial
    adi_kernel<<<(B / S) * CCH, 1024, SMEM_BYTES>>>(u, cc, (float*)d_out);
}

// round 5
// speedup vs baseline: 1.2177x; 1.2177x over previous
#include <cuda_runtime.h>

#define S 32
#define CCH 3
#define NSTEPS 4
#define DT_C 0.15f
#define EPS_C 1e-6f

// Precomputed Thomas factors: p = 1/denom, q = a/denom (== cstar since a==c).
// Layout: [step][channel][line][i] as float2.
__device__ float2 g_pqx[NSTEPS * CCH * S * S];
__device__ float2 g_pqy[NSTEPS * CCH * S * S];

__global__ void precompute_kernel(const float* __restrict__ alpha_base,
                                  const float* __restrict__ beta_base,
                                  const float* __restrict__ alpha_tc,
                                  const float* __restrict__ beta_tc) {
    int idx = blockIdx.x * blockDim.x + threadIdx.x;
    const int NLINES = NSTEPS * CCH * S;      // 384 per direction
    if (idx >= 2 * NLINES) return;
    int dir  = idx / NLINES;                  // 0 = x (solve along W), 1 = y (along H)
    int r    = idx % NLINES;
    int t    = r / (CCH * S);
    int c    = (r / S) % CCH;
    int line = r % S;                          // h for x-dir, w for y-dir

    float tv = (float)t * DT_C;
    const float* base = dir ? beta_base : alpha_base;
    const float* tc   = dir ? beta_tc   : alpha_tc;

    float raw[S];
    #pragma unroll
    for (int i = 0; i < S; i++) {
        int h = dir ? i : line;
        int w = dir ? line : i;
        int off = (c * S + h) * S + w;
        raw[i] = fmaxf(base[off] + tc[off] * tv, EPS_C);
    }
    // 3-tap replicate-padded smoothing along the solve dimension, times dt/DX^2
    float dt = dir ? DT_C : (DT_C * 0.5f);
    float cf[S];
    #pragma unroll
    for (int i = 0; i < S; i++) {
        float lm = raw[i == 0 ? 0 : i - 1];
        float rm = raw[i == S - 1 ? S - 1 : i + 1];
        cf[i] = (lm + raw[i] + rm) * (1.0f / 3.0f) * dt;
    }
    float2* out = dir ? g_pqy : g_pqx;
    long ob = ((long)(t * CCH + c) * S + line) * S;
    float cp = 0.0f;
    #pragma unroll
    for (int i = 0; i < S; i++) {
        float b = 1.0f + 2.0f * cf[i];
        if (i == 0 || i == S - 1) b = 1.0f + cf[i];
        float a = -cf[i];
        float denom = b - a * cp + EPS_C;     // matches reference (+EPS every step)
        float p = 1.0f / denom;
        float q = a * p;                      // also equals cstar_i (a == c)
        cp = q;
        out[ob + i] = make_float2(p, q);
    }
}

// One tridiagonal sweep of 32 independent systems (lane = batch) for one line.
// Coefficients come from a per-line smem table via *broadcast* LDS (all lanes
// read the same address -> 1 wavefront). asm volatile pins each load at its
// use site so ptxas cannot hoist 16 float4 live values and spill r[] (the R2
// failure mode). caddr = shared-space byte address of this line's float2[32].
template<bool COL, bool IN_SMEM, bool OUT_SMEM>
__device__ __forceinline__ void solve32(float* __restrict__ tile, float (&r)[S],
                                        unsigned caddr, int line, int lane,
                                        float scale) {
    float prev = 0.0f;
    #pragma unroll
    for (int i = 0; i < S; i++) {
        float p, q;
        asm volatile("ld.shared.v2.f32 {%0,%1},[%2];"
                     : "=f"(p), "=f"(q) : "r"(caddr + 8u * i));
        float d;
        if (IN_SMEM) {
            int e = COL ? (i * S + line) : (line * S + i);
            d = tile[e * 33 + lane];
        } else {
            d = r[i];
        }
        prev = fmaf(-q, prev, d * p);         // (d - a*prev)/denom
        r[i] = prev;
    }
    float x = r[S - 1];                       // cstar[N-1] irrelevant (x_N = 0)
    r[S - 1] = x * scale;
    if (OUT_SMEM) {
        int e = COL ? ((S - 1) * S + line) : (line * S + (S - 1));
        tile[e * 33 + lane] = x * scale;
    }
    #pragma unroll
    for (int i = S - 2; i >= 0; i--) {
        float q;                               // cstar_i == q_i
        asm volatile("ld.shared.f32 %0,[%1];"
                     : "=f"(q) : "r"(caddr + 8u * i + 4u));
        x = fmaf(-q, x, r[i]);
        r[i] = x * scale;
        if (OUT_SMEM) {
            int e = COL ? (i * S + line) : (line * S + i);
            tile[e * 33 + lane] = x * scale;
        }
    }
}

// Dynamic smem: [ scx2: 4096 float2 | scy2: 4096 float2 | tile: 33792 floats ]
#define COEF_F2_PER_DIR (NSTEPS * S * S)          // 4096 float2 = 32KB per dir
#define SMEM_BYTES (2 * COEF_F2_PER_DIR * 8 + S * S * 33 * 4)  // 200704 B

__global__ void __launch_bounds__(1024, 1)
adi_kernel(const float* __restrict__ U, const float* __restrict__ coupling,
           float* __restrict__ Out) {
    extern __shared__ float smem[];
    float2* scx2 = (float2*)smem;
    float2* scy2 = scx2 + COEF_F2_PER_DIR;
    float*  tile = (float*)(scy2 + COEF_F2_PER_DIR);

    int c    = blockIdx.x % CCH;
    int g    = blockIdx.x / CCH;
    int warp = threadIdx.x >> 5;
    int lane = threadIdx.x & 31;
    int tid  = threadIdx.x;

    // Stage this channel's (p,q) tables into smem (4 steps x 32 lines each dir).
    const float4* gx4 = (const float4*)g_pqx;
    const float4* gy4 = (const float4*)g_pqy;
    float4* sx4 = (float4*)scx2;
    float4* sy4 = (float4*)scy2;
    #pragma unroll
    for (int k = tid; k < NSTEPS * 512; k += 1024) {
        int t = k >> 9;                        // 512 float4 per step per dir
        int j = k & 511;
        sx4[t * 512 + j] = gx4[(t * CCH + c) * 512 + j];
        sy4[t * 512 + j] = gy4[(t * CCH + c) * 512 + j];
    }

    unsigned sbx = (unsigned)__cvta_generic_to_shared(scx2);
    unsigned sby = (unsigned)__cvta_generic_to_shared(scy2);

    size_t base = ((size_t)g * S) * (CCH * S * S) + (size_t)c * (S * S);
    const float* ub = U + base + (size_t)warp * (CCH * S * S);  // batch = g*32+warp

    // Coalesced load (128B/line) -> conflict-free STS thanks to the 33-pad.
    #pragma unroll
    for (int k = 0; k < S; k++)
        tile[(k * S + lane) * 33 + warp] = __ldg(ub + k * S + lane);

    float scal = coupling[c * CCH + c];       // einsum 'cc,bchw->bchw' = diag scale
    __syncthreads();

    float r[S];
    #pragma unroll 1
    for (int t = 0; t < NSTEPS; t++) {
        unsigned cax = sbx + (unsigned)((t * S + warp) * S) * 8u;
        unsigned cay = sby + (unsigned)((t * S + warp) * S) * 8u;

        // x half-step #1: rows. Input comes from registers for t>0 (fused with
        // previous step's x2 output, same warp/lane/addresses -> no barrier).
        if (t == 0) solve32<false, true,  true>(tile, r, cax, warp, lane, 1.0f);
        else        solve32<false, false, true>(tile, r, cax, warp, lane, 1.0f);
        __syncthreads();

        // y full step: columns (r reused as scratch; rows already flushed).
        solve32<true, true, true>(tile, r, cay, warp, lane, 1.0f);
        __syncthreads();

        // x half-step #2: rows, with channel coupling folded into the output.
        // For t<3 keep the result in registers only (next x1 consumes it).
        if (t == NSTEPS - 1) solve32<false, true, true >(tile, r, cax, warp, lane, scal);
        else                 solve32<false, true, false>(tile, r, cax, warp, lane, scal);
        if (t == NSTEPS - 1) __syncthreads();
    }

    float* ob = Out + base + (size_t)warp * (CCH * S * S);
    #pragma unroll
    for (int k = 0; k < S; k++)
        ob[k * S + lane] = tile[(k * S + lane) * 33 + warp];
}

extern "C" void kernel_launch(void* const* d_in, const int* in_sizes, int n_in,
                              void* d_out, int out_size) {
    (void)n_in; (void)out_size;
    const float* u   = (const float*)d_in[0];
    const float* ab  = (const float*)d_in[1];
    const float* bb  = (const float*)d_in[2];
    const float* atc = (const float*)d_in[3];
    const float* btc = (const float*)d_in[4];
    const float* cc  = (const float*)d_in[5];
    int B = in_sizes[0] / (CCH * S * S);      // 16384

    cudaFuncSetAttribute(adi_kernel, cudaFuncAttributeMaxDynamicSharedMemorySize,
                         SMEM_BYTES);

    precompute_kernel<<<3, 256>>>(ab, bb, atc, btc);   // 768 lines, trivial
    adi_kernel<<<(B / S) * CCH, 1024, SMEM_BYTES>>>(u, cc, (float*)d_out);
}